// round 1
// baseline (speedup 1.0000x reference)
#include <cuda_runtime.h>
#include <math.h>

// ---------------------------------------------------------------------------
// Problem constants: B=8, T=10, H=W=64, Cin=1, F=64, 4F=256, k=3x3 SAME.
// Output: [2 layers][2 (h,c)][8][64][64][64] fp32 = 8,388,608 floats.
// ---------------------------------------------------------------------------

#define HW        64
#define FDIM      64
#define C4        256
#define NPIX      4096           // 64*64
#define SEG       2097152        // 8*4096*64  (one h or c tensor)

// Scratch (device globals: the sanctioned allocation-free workaround)
__device__ float g_xg0[10 * 8 * NPIX * C4];   // 83,886,080 floats
__device__ float g_xg1[10 * 8 * NPIX * C4];
__device__ float g_out0[10 * 8 * NPIX * FDIM];
__device__ float g_h[2][SEG];
__device__ float g_c[SEG];

__device__ __forceinline__ float hsig(float x) {
    return fminf(fmaxf(0.2f * x + 0.5f, 0.0f), 1.0f);
}

// ---------------------------------------------------------------------------
// Zero-init h (ping buffer) and c
// ---------------------------------------------------------------------------
__global__ void zero_hc() {
    int i = blockIdx.x * blockDim.x + threadIdx.x;
    if (i < SEG) { g_h[0][i] = 0.0f; g_c[i] = 0.0f; }
}

// Copy final h (in g_h[0] after 10 steps) and c into the output stack
__global__ void gather_out(float* __restrict__ out, int layer) {
    int i = blockIdx.x * blockDim.x + threadIdx.x;
    if (i < SEG) {
        out[(size_t)layer * 2 * SEG + i]       = g_h[0][i];
        out[(size_t)layer * 2 * SEG + SEG + i] = g_c[i];
    }
}

// ---------------------------------------------------------------------------
// Layer-0 input conv (Cin=1): xg0[img][pos][256] = b0 + conv(x_img, Wx0)
// img = b*10 + t (matches x layout [B,T,H,W,1]). 16x16 tile per block,
// thread = output channel, weights in registers, patch broadcast from smem.
// ---------------------------------------------------------------------------
__global__ void conv_l0(const float* __restrict__ x, const float* __restrict__ w,
                        const float* __restrict__ b, float* __restrict__ xg) {
    __shared__ float ps[18 * 18];
    __shared__ float ws[9 * C4];

    int img = blockIdx.y;
    int by0 = (blockIdx.x >> 2) * 16;
    int bx0 = (blockIdx.x & 3) * 16;
    int tid = threadIdx.x;

    for (int i = tid; i < 324; i += 256) {
        int ly = i / 18, lx = i - ly * 18;
        int gy = by0 + ly - 1, gx = bx0 + lx - 1;
        float v = 0.0f;
        if (gy >= 0 && gy < HW && gx >= 0 && gx < HW)
            v = x[(size_t)img * NPIX + gy * HW + gx];
        ps[i] = v;
    }
    for (int i = tid; i < 9 * C4; i += 256) ws[i] = w[i];
    __syncthreads();

    float wr[9];
#pragma unroll
    for (int tp = 0; tp < 9; ++tp) wr[tp] = ws[tp * C4 + tid];
    float bv = b[tid];

    for (int p = 0; p < 256; ++p) {
        int py = p >> 4, px = p & 15;
        float a = bv;
#pragma unroll
        for (int tp = 0; tp < 9; ++tp) {
            int dy = tp / 3, dx = tp - 3 * dy;
            a += ps[(py + dy) * 18 + (px + dx)] * wr[tp];
        }
        xg[((size_t)img * NPIX + (by0 + py) * HW + (bx0 + px)) * C4 + tid] = a;
    }
}

// ---------------------------------------------------------------------------
// Core implicit-GEMM 3x3 conv, 64 in -> 256 out channels, 8x8 spatial tile.
// MODE STEP=1: acc init from xg (bias included), fused LSTM epilogue:
//     c' = hs(f)*c + hs(i)*tanh(g);  h' = hs(o)*tanh(c');  optional out_seq.
// MODE STEP=0: acc init from bias; stores raw gates to out_gates (xg buffer).
//
// smem: hsm[64ch][10][10] patch (ch-major -> h reads are warp broadcasts),
//       wsm 32x256 weight chunk stored j/cc-permuted for conflict-free LDS.128.
// Thread (pc=tid/16, cc=tid%16): 4 positions x 16 channels register tile.
// ---------------------------------------------------------------------------
template <int STEP>
__global__ __launch_bounds__(256, 2)
void conv_main(const float* __restrict__ in,        // [nimg][64][64][64]
               const float* __restrict__ W,         // [3][3][64][256]
               const float* __restrict__ xg_or_b,   // STEP: xg base; else bias[256]
               float* __restrict__ out_gates,       // !STEP: gates out
               float* __restrict__ cbuf,
               float* __restrict__ hout,
               float* __restrict__ outseq,
               int t) {
    extern __shared__ float smem[];
    float*  hsm  = smem;                       // 6400 floats
    float4* wsm4 = (float4*)(smem + 6400);     // 2048 float4 (8192 floats)

    int img = blockIdx.y;
    int by0 = (blockIdx.x >> 3) * 8;
    int bx0 = (blockIdx.x & 7) * 8;
    int tid = threadIdx.x;
    int pc = tid >> 4, cc = tid & 15;
    int py = pc >> 1, px0 = (pc & 1) * 4;

    // Load 10x10x64 input patch, channel-major in smem
    const float* inb = in + (size_t)img * NPIX * FDIM;
    for (int i = tid; i < 6400; i += 256) {
        int pix = i >> 6, ch = i & 63;
        int ly = pix / 10, lx = pix - ly * 10;
        int gy = by0 + ly - 1, gx = bx0 + lx - 1;
        float v = 0.0f;
        if (gy >= 0 && gy < HW && gx >= 0 && gx < HW)
            v = inb[((gy << 6) + gx) * FDIM + ch];
        hsm[ch * 100 + pix] = v;
    }

    // Init accumulators
    float4 acc[4][4];
    if (STEP) {
        const float* xgb = xg_or_b + (size_t)(img * 10 + t) * NPIX * C4;
#pragma unroll
        for (int i = 0; i < 4; ++i) {
            int pos = pc * 4 + i;
            int gy = by0 + (pos >> 3), gx = bx0 + (pos & 7);
            const float4* xp = (const float4*)(xgb + (size_t)((gy << 6) + gx) * C4);
#pragma unroll
            for (int j = 0; j < 4; ++j) acc[i][j] = xp[(cc << 2) + j];
        }
    } else {
        const float4* bp = (const float4*)xg_or_b;
        float4 bv[4];
#pragma unroll
        for (int j = 0; j < 4; ++j) bv[j] = bp[(cc << 2) + j];
#pragma unroll
        for (int i = 0; i < 4; ++i)
#pragma unroll
            for (int j = 0; j < 4; ++j) acc[i][j] = bv[j];
    }

    // Main loop: 9 taps x 2 chunks of 32 input channels
    for (int tap = 0; tap < 9; ++tap) {
        int dy = tap / 3, dx = tap - 3 * dy;
        for (int chunk = 0; chunk < 2; ++chunk) {
            __syncthreads();   // (1st iter: hsm ready; later: previous wsm reads done)
            const float4* wg = (const float4*)(W + (size_t)(tap * 64 + chunk * 32) * C4);
#pragma unroll
            for (int i = 0; i < 8; ++i) {
                int gi = tid + i * 256;                // 0..2047 float4s
                int kc = gi >> 6, c4 = gi & 63;        // c4 = cc*4 + j in source
                wsm4[(kc << 6) + ((c4 & 3) << 4) + (c4 >> 2)] = wg[gi];
            }
            __syncthreads();

            const float* hp = hsm + (chunk * 32) * 100 + (py + dy) * 10 + (px0 + dx);
#pragma unroll 4
            for (int kc = 0; kc < 32; ++kc) {
                const float4* wr2 = wsm4 + (kc << 6) + cc;
                float4 wv[4];
#pragma unroll
                for (int j = 0; j < 4; ++j) wv[j] = wr2[j * 16];
                float hv[4];
#pragma unroll
                for (int i = 0; i < 4; ++i) hv[i] = hp[kc * 100 + i];
#pragma unroll
                for (int i = 0; i < 4; ++i) {
#pragma unroll
                    for (int j = 0; j < 4; ++j) {
                        acc[i][j].x += hv[i] * wv[j].x;
                        acc[i][j].y += hv[i] * wv[j].y;
                        acc[i][j].z += hv[i] * wv[j].z;
                        acc[i][j].w += hv[i] * wv[j].w;
                    }
                }
            }
        }
    }

    if (STEP) {
        // Exchange gates through smem (i/f/g/o live in different threads)
        __syncthreads();
        float4* g4 = (float4*)smem;   // 64 pos x 64 float4 = 64 KB
#pragma unroll
        for (int i = 0; i < 4; ++i) {
            int pos = pc * 4 + i;
#pragma unroll
            for (int j = 0; j < 4; ++j) g4[(pos << 6) + (cc << 2) + j] = acc[i][j];
        }
        __syncthreads();
#pragma unroll
        for (int r = 0; r < 4; ++r) {
            int wk = r * 256 + tid;
            int pos = wk >> 4, fq = wk & 15;
            const float* gp = smem + (pos << 8);
            float4 ig = *(const float4*)(gp +       (fq << 2));
            float4 fg = *(const float4*)(gp +  64 + (fq << 2));
            float4 gg = *(const float4*)(gp + 128 + (fq << 2));
            float4 og = *(const float4*)(gp + 192 + (fq << 2));
            int gy = by0 + (pos >> 3), gx = bx0 + (pos & 7);
            size_t hidx = ((size_t)img * NPIX + (gy << 6) + gx) * FDIM + (fq << 2);
            float4 cold = *(const float4*)(cbuf + hidx);
            float4 cn, hn;
            cn.x = hsig(fg.x) * cold.x + hsig(ig.x) * tanhf(gg.x);
            cn.y = hsig(fg.y) * cold.y + hsig(ig.y) * tanhf(gg.y);
            cn.z = hsig(fg.z) * cold.z + hsig(ig.z) * tanhf(gg.z);
            cn.w = hsig(fg.w) * cold.w + hsig(ig.w) * tanhf(gg.w);
            hn.x = hsig(og.x) * tanhf(cn.x);
            hn.y = hsig(og.y) * tanhf(cn.y);
            hn.z = hsig(og.z) * tanhf(cn.z);
            hn.w = hsig(og.w) * tanhf(cn.w);
            *(float4*)(cbuf + hidx) = cn;
            *(float4*)(hout + hidx) = hn;
            if (outseq) {
                size_t oidx = ((size_t)(img * 10 + t) * NPIX + (gy << 6) + gx) * FDIM + (fq << 2);
                *(float4*)(outseq + oidx) = hn;
            }
        }
    } else {
        float* ob = out_gates + (size_t)img * NPIX * C4;
#pragma unroll
        for (int i = 0; i < 4; ++i) {
            int pos = pc * 4 + i;
            int gy = by0 + (pos >> 3), gx = bx0 + (pos & 7);
            float4* op = (float4*)(ob + (size_t)((gy << 6) + gx) * C4);
#pragma unroll
            for (int j = 0; j < 4; ++j) op[(cc << 2) + j] = acc[i][j];
        }
    }
}

// ---------------------------------------------------------------------------
// Host: full encoder pipeline on the default stream (graph-capturable).
// ---------------------------------------------------------------------------
extern "C" void kernel_launch(void* const* d_in, const int* in_sizes, int n_in,
                              void* d_out, int out_size) {
    const float* x   = (const float*)d_in[0];
    const float* Wx0 = (const float*)d_in[1];
    const float* Wh0 = (const float*)d_in[2];
    const float* b0  = (const float*)d_in[3];
    const float* Wx1 = (const float*)d_in[4];
    const float* Wh1 = (const float*)d_in[5];
    const float* b1  = (const float*)d_in[6];
    float* out = (float*)d_out;

    float *xg0, *xg1, *out0, *hbase, *cbuf;
    cudaGetSymbolAddress((void**)&xg0,  g_xg0);
    cudaGetSymbolAddress((void**)&xg1,  g_xg1);
    cudaGetSymbolAddress((void**)&out0, g_out0);
    cudaGetSymbolAddress((void**)&hbase, g_h);
    cudaGetSymbolAddress((void**)&cbuf, g_c);
    float* hb[2] = { hbase, hbase + SEG };

    cudaFuncSetAttribute(conv_main<1>, cudaFuncAttributeMaxDynamicSharedMemorySize, 65536);
    cudaFuncSetAttribute(conv_main<0>, cudaFuncAttributeMaxDynamicSharedMemorySize, 65536);

    // Layer 0: batched input conv (Cin=1) for all 80 (b,t) images
    conv_l0<<<dim3(16, 80), 256>>>(x, Wx0, b0, xg0);

    // Layer 0 recurrence
    zero_hc<<<2048, 1024>>>();
    for (int t = 0; t < 10; ++t)
        conv_main<1><<<dim3(64, 8), 256, 65536>>>(
            hb[t & 1], Wh0, xg0, nullptr, cbuf, hb[(t + 1) & 1], out0, t);
    gather_out<<<2048, 1024>>>(out, 0);

    // Layer 1: batched input conv over out0 (80 images, Cin=64)
    conv_main<0><<<dim3(64, 80), 256, 65536>>>(
        out0, Wx1, b1, xg1, nullptr, nullptr, nullptr, 0);

    // Layer 1 recurrence
    zero_hc<<<2048, 1024>>>();
    for (int t = 0; t < 10; ++t)
        conv_main<1><<<dim3(64, 8), 256, 65536>>>(
            hb[t & 1], Wh1, xg1, nullptr, cbuf, hb[(t + 1) & 1], nullptr, t);
    gather_out<<<2048, 1024>>>(out, 1);

    (void)in_sizes; (void)n_in; (void)out_size;
}